// round 17
// baseline (speedup 1.0000x reference)
#include <cuda_runtime.h>
#include <math.h>
#include <cstdint>

#define NB 32768
#define ND 128
#define NH 512
#define NE 16
#define CHUNK 64
#define NCHUNKS 8
#define MAX_TILES 320
#define NBLOCKS 256
#define NTHREADS 256             // 8 warps: 4(m) x 2(n)

// smem word offsets
#define OFF_X 0                  // X packed: 16384 words (64 KB)
#define OFF_HW 16384             // warp-private H: 8 x 1024 words (32 KB)
#define OFF_W 24576              // 2 slots x 16384 words (W1c 8192 | W2c 8192)
#define SLOT_PAIR 16384
#define SMEM_WORDS (OFF_W + 2 * SLOT_PAIR + 128)
#define SMEM_BYTES (SMEM_WORDS * 4)     // 229888 B

#define NW1 (NE * ND * NH)
#define NW2 (NE * NH * ND)

// ---------------- scratch ----------------
__device__ int g_counts[NE];
__device__ int g_bucket[NE * NB];
__device__ int g_sched_e[MAX_TILES];
__device__ int g_sched_base[MAX_TILES];
__device__ int g_ntiles;
__device__ int g_work;
__device__ float g_w1p[NW1];     // w1 tf32, frag-pair packed per (expert, chunk)
__device__ float g_w2p[NW2];     // w2 tf32, frag-pair packed per (expert, chunk)

// ---------------- helpers ----------------
__device__ __forceinline__ uint32_t smem_u32(const void* p) {
    uint32_t a;
    asm("{ .reg .u64 t; cvta.to.shared.u64 t, %1; cvt.u32.u64 %0, t; }" : "=r"(a) : "l"(p));
    return a;
}
__device__ __forceinline__ void cp16(uint32_t dst, const void* src) {
    asm volatile("cp.async.ca.shared.global [%0], [%1], 16;" :: "r"(dst), "l"(src));
}
#define CP_COMMIT() asm volatile("cp.async.commit_group;" ::: "memory")
#define CP_WAIT1()  asm volatile("cp.async.wait_group 1;" ::: "memory")

__device__ __forceinline__ uint32_t f2tf32(float f) {
    uint32_t r;
    asm("cvt.rna.tf32.f32 %0, %1;" : "=r"(r) : "f"(f));
    return r;
}
__device__ __forceinline__ float gelu_exact(float v) {
    return 0.5f * v * (1.0f + erff(v * 0.70710678118654752440f));
}
__device__ __forceinline__ void mma_tf32(float c[4], const uint32_t a[4], const uint32_t b[2]) {
    asm volatile(
        "mma.sync.aligned.m16n8k8.row.col.f32.tf32.tf32.f32 "
        "{%0,%1,%2,%3}, {%4,%5,%6,%7}, {%8,%9}, {%0,%1,%2,%3};\n"
        : "+f"(c[0]), "+f"(c[1]), "+f"(c[2]), "+f"(c[3])
        : "r"(a[0]), "r"(a[1]), "r"(a[2]), "r"(a[3]), "r"(b[0]), "r"(b[1]));
}

// G1 warp GEMM (A/X packed float4 frags, B packed float2 frag-pairs).
template <int KS, int NT, int NC>
__device__ __forceinline__ void gemm_packed(const float* __restrict__ A,
                                            const float* __restrict__ B,
                                            float C[2][NT][4],
                                            int m16b, int nbase, int gid, int tig) {
    const float4* Ap = (const float4*)A;
    const float2* Bp = (const float2*)B;
    const int tr = (tig + gid) & 3;
#pragma unroll
    for (int ks = 0; ks < KS; ks++) {
        float4 av[2];
#pragma unroll
        for (int mt = 0; mt < 2; mt++)
            av[mt] = Ap[(((m16b + mt) * KS + ks) * 8 + gid) * 4 + tr];
        float2 bv[NT];
#pragma unroll
        for (int nt = 0; nt < NT; nt++)
            bv[nt] = Bp[(ks * NC + nbase + nt * 8 + gid) * 4 + tig];
#pragma unroll
        for (int mt = 0; mt < 2; mt++) {
            uint32_t a[4] = {__float_as_uint(av[mt].x), __float_as_uint(av[mt].y),
                             __float_as_uint(av[mt].z), __float_as_uint(av[mt].w)};
#pragma unroll
            for (int nt = 0; nt < NT; nt++) {
                uint32_t b[2] = {__float_as_uint(bv[nt].x), __float_as_uint(bv[nt].y)};
                mma_tf32(C[mt][nt], a, b);
            }
        }
    }
}

// ---------------------------------------------------------------------------
// prep: zero counts + convert/pack weights to tf32 frag-pair layout.
// ---------------------------------------------------------------------------
__global__ void prep_kernel(const float* __restrict__ w1,
                            const float* __restrict__ w2) {
    int i0 = blockIdx.x * blockDim.x + threadIdx.x;
    if (i0 < NE) g_counts[i0] = 0;
    for (int i = i0; i < NW1; i += gridDim.x * blockDim.x) {
        int e = i >> 16;
        int rem = i & 65535;
        {   // w1 [e][d][h] -> chunk (k=d, n=h%64) packed
            int d = rem >> 9;
            int h = rem & 511;
            int hc = h >> 6, n = h & 63;
            int ks = d >> 3, kr = d & 7, t = kr & 3, khi = kr >> 2;
            int idx = ((((e * 8 + hc) * 16 + ks) * 64 + n) * 4 + t) * 2 + khi;
            g_w1p[idx] = __uint_as_float(f2tf32(w1[i]));
        }
        {   // w2 [e][h][d] -> chunk (k=h%64, n=d) packed
            int h = rem >> 7;
            int d = rem & 127;
            int hc = h >> 6, hl = h & 63;
            int ks = hl >> 3, kr = hl & 7, t = kr & 3, khi = kr >> 2;
            int idx = ((((e * 8 + hc) * 8 + ks) * 128 + d) * 4 + t) * 2 + khi;
            g_w2p[idx] = __uint_as_float(f2tf32(w2[i]));
        }
    }
}

__global__ void route_kernel(const float* __restrict__ x,
                             const float* __restrict__ wg,
                             const float* __restrict__ bg) {
    __shared__ float swg[ND * NE];
    __shared__ float sbg[NE];
    for (int i = threadIdx.x; i < ND * NE; i += blockDim.x) swg[i] = wg[i];
    if (threadIdx.x < NE) sbg[threadIdx.x] = bg[threadIdx.x];
    __syncthreads();

    int b = blockIdx.x * blockDim.x + threadIdx.x;
    if (b >= NB) return;
    const float* xr = x + (size_t)b * ND;

    float acc[NE];
#pragma unroll
    for (int e = 0; e < NE; e++) acc[e] = sbg[e];
#pragma unroll 4
    for (int d = 0; d < ND; d++) {
        float xv = __ldg(xr + d);
#pragma unroll
        for (int e = 0; e < NE; e++) acc[e] = fmaf(xv, swg[d * NE + e], acc[e]);
    }
    float best = acc[0]; int bi = 0;
#pragma unroll
    for (int e = 1; e < NE; e++)
        if (acc[e] > best) { best = acc[e]; bi = e; }
    int pos = atomicAdd(&g_counts[bi], 1);
    g_bucket[bi * NB + pos] = b;
}

__global__ void sched_kernel() {
    int e = threadIdx.x;
    int tiles = (e < NE) ? ((g_counts[e] + 127) >> 7) : 0;
    int inc = tiles;
#pragma unroll
    for (int d = 1; d < 32; d <<= 1) {
        int v = __shfl_up_sync(0xFFFFFFFFu, inc, d);
        if (threadIdx.x >= d) inc += v;
    }
    int off = inc - tiles;
    if (e < NE)
        for (int t = 0; t < tiles; t++) {
            g_sched_e[off + t] = e;
            g_sched_base[off + t] = t * 128;
        }
    if (threadIdx.x == 31) { g_ntiles = inc; g_work = 0; }
}

// ---------------------------------------------------------------------------
// Persistent fused expert kernel. Per chunk: G1 (warp cols ng*32..+32) ->
// gelu -> warp-private H (syncwarp only) -> split-K G2 over full N=128 into
// c2[2][16][4]. End: warp-pair k-reduction through dead X buffer, then STG.
// ---------------------------------------------------------------------------
__global__ __launch_bounds__(NTHREADS, 1)
void expert_gemm_fused(const float* __restrict__ x,
                       float* __restrict__ out) {
    extern __shared__ __align__(128) float smem[];

    const uint32_t sb = smem_u32(smem);
    const int tid = threadIdx.x;
    const int lane = tid & 31;
    const int warp = tid >> 5;
    const int mg = warp & 3;          // m-group: rows [mg*32, +32)
    const int ng = warp >> 2;         // k/n split group (0..1)
    const int gid = lane >> 2;
    const int tig = lane & 3;
    float* Xp = smem + OFF_X;
    float* Hw = smem + OFF_HW + warp * 1024;   // warp-private H (4 KB)
    int* stok = (int*)(smem + OFF_W + 2 * SLOT_PAIR);
    __shared__ int s_tile;

    const int ntiles = g_ntiles;

    for (;;) {
        if (tid == 0) s_tile = atomicAdd(&g_work, 1);
        __syncthreads();
        const int t = s_tile;
        if (t >= ntiles) break;

        const int e = g_sched_e[t];
        const int base = g_sched_base[t];
        const int count = g_counts[e];
        const float* w1e = g_w1p + (size_t)e * 8 * 8192;
        const float* w2e = g_w2p + (size_t)e * 8 * 8192;

        // ---- prologue: load chunk 0 -> slot 0, chunk 1 -> slot 1 ----
#pragma unroll
        for (int c = 0; c < 2; c++) {
            uint32_t wb = sb + (OFF_W + c * SLOT_PAIR) * 4;
#pragma unroll
            for (int i = 0; i < 8; i++) {
                int seg = tid + i * NTHREADS;
                cp16(wb + seg * 16, w1e + (size_t)c * 8192 + seg * 4);
            }
#pragma unroll
            for (int i = 0; i < 8; i++) {
                int seg = tid + i * NTHREADS;
                cp16(wb + 8192 * 4 + seg * 16, w2e + (size_t)c * 8192 + seg * 4);
            }
            CP_COMMIT();
        }

        // ---- X tile gather -> tf32, frag-packed (overlaps cp.async) ----
        {
            int row = tid >> 1;
            int half = (tid & 1) * 64;
            int gi = base + row;
            int tok = (gi < count) ? g_bucket[e * NB + gi] : -1;
            if ((tid & 1) == 0) stok[row] = tok;
            int m16 = row >> 4, r7 = row & 7, hi = (row >> 3) & 1;
            if (tok >= 0) {
                const float4* src = (const float4*)(x + (size_t)tok * ND + half);
#pragma unroll
                for (int g = 0; g < 8; g++) {
                    int ks = (half >> 3) + g;
                    float4 v0 = src[g * 2], v1 = src[g * 2 + 1];
                    float vals[8] = {v0.x, v0.y, v0.z, v0.w, v1.x, v1.y, v1.z, v1.w};
                    int wb = ((m16 * 16 + ks) * 8 + r7) * 16 + hi;
#pragma unroll
                    for (int kk = 0; kk < 8; kk++) {
                        int tp = ((kk & 3) + r7) & 3;
                        Xp[wb + tp * 4 + (kk >> 2) * 2] =
                            __uint_as_float(f2tf32(vals[kk]));
                    }
                }
            } else {
#pragma unroll
                for (int g = 0; g < 8; g++) {
                    int ks = (half >> 3) + g;
                    int wb = ((m16 * 16 + ks) * 8 + r7) * 16 + hi;
#pragma unroll
                    for (int kk = 0; kk < 8; kk++) {
                        int tp = ((kk & 3) + r7) & 3;
                        Xp[wb + tp * 4 + (kk >> 2) * 2] = 0.0f;
                    }
                }
            }
        }

        float c2[2][16][4];
#pragma unroll
        for (int mt = 0; mt < 2; mt++)
#pragma unroll
            for (int nt = 0; nt < 16; nt++)
#pragma unroll
                for (int q = 0; q < 4; q++) c2[mt][nt][q] = 0.0f;

#pragma unroll 1
        for (int hc = 0; hc < NCHUNKS; hc++) {
            CP_WAIT1();
            __syncthreads();      // chunk hc pair loaded; X ready (hc=0)

            const float* W1c = smem + OFF_W + (hc & 1) * SLOT_PAIR;
            const float* W2c = W1c + 8192;

            // ---- G1: c1 = X @ W1c[:, ng*32..+32)  (NT=4) ----
            float c1[2][4][4];
#pragma unroll
            for (int mt = 0; mt < 2; mt++)
#pragma unroll
                for (int nt = 0; nt < 4; nt++)
#pragma unroll
                    for (int q = 0; q < 4; q++) c1[mt][nt][q] = 0.0f;

            gemm_packed<16, 4, 64>(Xp, W1c, c1, mg * 2, ng * 32, gid, tig);

            // ---- gelu -> warp-private H (A-frag packed), no block barrier ----
            __syncwarp();
#pragma unroll
            for (int mt = 0; mt < 2; mt++) {
#pragma unroll
                for (int nt = 0; nt < 4; nt++) {   // kt = nt
                    int wb = ((mt * 4 + nt) * 8 + gid) * 16;
#pragma unroll
                    for (int q = 0; q < 4; q++) {
                        int k7 = tig * 2 + (q & 1);
                        int tp = ((k7 & 3) + gid) & 3;
                        int slot = (k7 >> 2) * 2 + (q >> 1);
                        Hw[wb + tp * 4 + slot] =
                            __uint_as_float(f2tf32(gelu_exact(c1[mt][nt][q])));
                    }
                }
            }
            __syncwarp();

            // ---- G2 split-K: c2 += H(warp k-quarter) @ W2c[ks=ng*4+kt] ----
            const float4* Hp4 = (const float4*)Hw;
            const float2* Bp = (const float2*)W2c;
            const int tr = (tig + gid) & 3;
#pragma unroll
            for (int nhalf = 0; nhalf < 2; nhalf++) {
#pragma unroll
                for (int kt = 0; kt < 4; kt++) {
                    int ks = ng * 4 + kt;
                    float4 av[2];
#pragma unroll
                    for (int mt = 0; mt < 2; mt++)
                        av[mt] = Hp4[((mt * 4 + kt) * 8 + gid) * 4 + tr];
                    float2 bv[8];
#pragma unroll
                    for (int nt = 0; nt < 8; nt++)
                        bv[nt] = Bp[(ks * 128 + nhalf * 64 + nt * 8 + gid) * 4 + tig];
#pragma unroll
                    for (int mt = 0; mt < 2; mt++) {
                        uint32_t a[4] = {__float_as_uint(av[mt].x), __float_as_uint(av[mt].y),
                                         __float_as_uint(av[mt].z), __float_as_uint(av[mt].w)};
#pragma unroll
                        for (int nt = 0; nt < 8; nt++) {
                            uint32_t b[2] = {__float_as_uint(bv[nt].x), __float_as_uint(bv[nt].y)};
                            mma_tf32(c2[mt][nhalf * 8 + nt], a, b);
                        }
                    }
                }
            }
            __syncthreads();      // all warps done with slot hc&1

            // ---- load chunk hc+2 into freed slot ----
            if (hc + 2 < NCHUNKS) {
                uint32_t wb = sb + (OFF_W + (hc & 1) * SLOT_PAIR) * 4;
                const float* s1 = w1e + (size_t)(hc + 2) * 8192;
                const float* s2 = w2e + (size_t)(hc + 2) * 8192;
#pragma unroll
                for (int i = 0; i < 8; i++) {
                    int seg = tid + i * NTHREADS;
                    cp16(wb + seg * 16, s1 + seg * 4);
                }
#pragma unroll
                for (int i = 0; i < 8; i++) {
                    int seg = tid + i * NTHREADS;
                    cp16(wb + 8192 * 4 + seg * 16, s2 + seg * 4);
                }
            }
            CP_COMMIT();
        }

        // ---- epilogue: split-K reduce via dead X buffer ----
        // warp (mg,ng) stores its partial for the half it will NOT finalize.
        {
            float* reg0 = smem + OFF_X + (mg * 2 + (1 - ng)) * 2048;
#pragma unroll
            for (int mt = 0; mt < 2; mt++)
#pragma unroll
                for (int nt = 0; nt < 8; nt++) {
                    float4 v = make_float4(c2[mt][(1 - ng) * 8 + nt][0],
                                           c2[mt][(1 - ng) * 8 + nt][1],
                                           c2[mt][(1 - ng) * 8 + nt][2],
                                           c2[mt][(1 - ng) * 8 + nt][3]);
                    *(float4*)(reg0 + ((mt * 8 + nt) * 32 + lane) * 4) = v;
                }
        }
        __syncthreads();
        // finalize own half: add peer partial, write out.
        {
            const float* regi = smem + OFF_X + (mg * 2 + ng) * 2048;
#pragma unroll
            for (int mt = 0; mt < 2; mt++) {
                int r0 = mg * 32 + mt * 16 + gid;
#pragma unroll
                for (int nt = 0; nt < 8; nt++) {
                    float4 p = *(const float4*)(regi + ((mt * 8 + nt) * 32 + lane) * 4);
                    float s0 = c2[mt][ng * 8 + nt][0] + p.x;
                    float s1 = c2[mt][ng * 8 + nt][1] + p.y;
                    float s2v = c2[mt][ng * 8 + nt][2] + p.z;
                    float s3 = c2[mt][ng * 8 + nt][3] + p.w;
                    int col = ng * 64 + nt * 8 + tig * 2;
                    int tokA = stok[r0];
                    int tokB = stok[r0 + 8];
                    if (tokA >= 0)
                        *(float2*)(out + (size_t)tokA * ND + col) = make_float2(s0, s1);
                    if (tokB >= 0)
                        *(float2*)(out + (size_t)tokB * ND + col) = make_float2(s2v, s3);
                }
            }
        }
        __syncthreads();   // X area reusable next tile
    }
}

// ---------------------------------------------------------------------------
extern "C" void kernel_launch(void* const* d_in, const int* in_sizes, int n_in,
                              void* d_out, int out_size) {
    const float* x  = (const float*)d_in[0];
    const float* w1 = (const float*)d_in[1];
    const float* w2 = (const float*)d_in[2];
    const float* wg = (const float*)d_in[3];
    const float* bg = (const float*)d_in[4];
    float* out = (float*)d_out;

    prep_kernel<<<512, 256>>>(w1, w2);
    route_kernel<<<NB / 256, 256>>>(x, wg, bg);
    sched_kernel<<<1, 32>>>();

    cudaFuncSetAttribute(expert_gemm_fused,
                         cudaFuncAttributeMaxDynamicSharedMemorySize, SMEM_BYTES);
    expert_gemm_fused<<<NBLOCKS, NTHREADS, SMEM_BYTES>>>(x, out);
}